// round 7
// baseline (speedup 1.0000x reference)
#include <cuda_runtime.h>

#define S_LEN   8192
#define DIM     64
#define WSZ     64
#define Q_TILE  128
#define KV_ROWS 256          // Q_TILE + 2*WSZ
#define THREADS 256
#define SMEM_BYTES (2 * KV_ROWS * DIM * 4)   // K + V fp32 tiles = 131072 B

// ---- packed f32x2 FMA (Blackwell; ptxas never auto-fuses this) ----
union F2U { float2 f; unsigned long long u; };
__device__ __forceinline__ float2 ffma2(float2 a, float2 b, float2 c) {
    F2U A, B, C, R; A.f = a; B.f = b; C.f = c;
    asm("fma.rn.f32x2 %0, %1, %2, %3;" : "=l"(R.u) : "l"(A.u), "l"(B.u), "l"(C.u));
    return R.f;
}
__device__ __forceinline__ float ex2(float x) {
    float r; asm("ex2.approx.ftz.f32 %0, %1;" : "=f"(r) : "f"(x)); return r;
}

__global__ void __launch_bounds__(THREADS, 1)
swa_kernel(const float* __restrict__ q, const float* __restrict__ k,
           const float* __restrict__ v, float* __restrict__ out)
{
    extern __shared__ float4 smem[];
    float4* Ks = smem;                   // [KV_ROWS][16] float4
    float4* Vs = smem + KV_ROWS * 16;

    const int tid = threadIdx.x;
    const int b   = blockIdx.x >> 6;               // 64 tiles per batch
    const int t0  = (blockIdx.x & 63) * Q_TILE;    // first query of tile

    // ---------- load K/V slab (rows t0-64 .. t0+191), zero-fill OOB ----------
    const float4* kg = (const float4*)(k + (size_t)b * S_LEN * DIM);
    const float4* vg = (const float4*)(v + (size_t)b * S_LEN * DIM);
    #pragma unroll
    for (int it = 0; it < (KV_ROWS * 16) / THREADS; ++it) {  // 16 iters
        int i    = tid + it * THREADS;
        int row  = i >> 4;
        int grow = t0 - WSZ + row;
        float4 kk = make_float4(0.f, 0.f, 0.f, 0.f);
        float4 vv = kk;
        if (grow >= 0 && grow < S_LEN) {
            kk = kg[grow * 16 + (i & 15)];
            vv = vg[grow * 16 + (i & 15)];
        }
        Ks[i] = kk; Vs[i] = vv;
    }

    // ---------- per-thread query registers ----------
    const int pl  = tid >> 2;         // pair index 0..63 -> queries 2pl, 2pl+1
    const int seg = tid & 3;          // dim segment: [seg*16, seg*16+16)
    const int qa  = t0 + 2 * pl;      // global query a (qb = qa+1)

    // fold softmax scale (1/8) and log2(e) into Q
    const float SC = 0.125f * 1.4426950408889634f;
    float2 qra[8], qrb[8];
    {
        const float2* ga = (const float2*)(q + ((size_t)b * S_LEN + qa)     * DIM + seg * 16);
        const float2* gb = (const float2*)(q + ((size_t)b * S_LEN + qa + 1) * DIM + seg * 16);
        #pragma unroll
        for (int i = 0; i < 8; ++i) {
            float2 ta = ga[i], tb = gb[i];
            qra[i] = make_float2(ta.x * SC, ta.y * SC);
            qrb[i] = make_float2(tb.x * SC, tb.y * SC);
        }
    }

    float2 oa[8], ob[8];
    #pragma unroll
    for (int i = 0; i < 8; ++i) { oa[i] = make_float2(0.f, 0.f); ob[i] = oa[i]; }
    float la = 0.f, lb = 0.f;

    __syncthreads();

    // ---------- warp-uniform absolute-key loop with broadcast smem reads ----------
    // smem row r holds key index (t0 - 64 + r). Query 2pl attends rows [2pl, 2pl+128].
    const int wid  = tid >> 5;
    const int gmin = WSZ - t0;                         // first globally valid row
    const int gmax = S_LEN - 1 + WSZ - t0;             // last  globally valid row
    int r_lo = 16 * wid;        if (r_lo < gmin) r_lo = gmin;
    int r_hi = 16 * wid + 143;  if (r_hi > gmax) r_hi = gmax;

    const int ra_lo = (2 * pl     > gmin) ? 2 * pl     : gmin;
    const int ra_hi = (2 * pl + 128 < gmax) ? 2 * pl + 128 : gmax;
    const int rb_lo = (2 * pl + 1 > gmin) ? 2 * pl + 1 : gmin;
    const int rb_hi = (2 * pl + 129 < gmax) ? 2 * pl + 129 : gmax;

    #pragma unroll 2
    for (int r = r_lo; r <= r_hi; ++r) {
        const float2* kr = (const float2*)&Ks[r * 16 + seg * 4];  // broadcast within seg group
        const float2* vr = (const float2*)&Vs[r * 16 + seg * 4];

        float2 kv[8];
        #pragma unroll
        for (int i = 0; i < 8; ++i) kv[i] = kr[i];

        float2 aa = make_float2(0.f, 0.f), ab = aa;
        #pragma unroll
        for (int i = 0; i < 8; ++i) {
            aa = ffma2(qra[i], kv[i], aa);
            ab = ffma2(qrb[i], kv[i], ab);
        }
        float sa = aa.x + aa.y;
        float sb = ab.x + ab.y;
        // reduce across the 4 seg lanes (lanes pl*4 .. pl*4+3)
        sa += __shfl_xor_sync(0xffffffffu, sa, 1);
        sa += __shfl_xor_sync(0xffffffffu, sa, 2);
        sb += __shfl_xor_sync(0xffffffffu, sb, 1);
        sb += __shfl_xor_sync(0xffffffffu, sb, 2);

        float ea = (r >= ra_lo && r <= ra_hi) ? ex2(sa) : 0.f;
        float eb = (r >= rb_lo && r <= rb_hi) ? ex2(sb) : 0.f;
        la += ea; lb += eb;

        float2 ea2 = make_float2(ea, ea);
        float2 eb2 = make_float2(eb, eb);
        #pragma unroll
        for (int i = 0; i < 8; ++i) {
            float2 vv = vr[i];
            oa[i] = ffma2(ea2, vv, oa[i]);
            ob[i] = ffma2(eb2, vv, ob[i]);
        }
    }

    // ---------- epilogue ----------
    const float inva = 1.f / la;
    const float invb = 1.f / lb;
    float2* ga = (float2*)(out + ((size_t)b * S_LEN + qa)     * DIM + seg * 16);
    float2* gb = (float2*)(out + ((size_t)b * S_LEN + qa + 1) * DIM + seg * 16);
    #pragma unroll
    for (int i = 0; i < 8; ++i) {
        ga[i] = make_float2(oa[i].x * inva, oa[i].y * inva);
        gb[i] = make_float2(ob[i].x * invb, ob[i].y * invb);
    }
}

extern "C" void kernel_launch(void* const* d_in, const int* in_sizes, int n_in,
                              void* d_out, int out_size)
{
    (void)in_sizes; (void)n_in; (void)out_size;
    const float* q = (const float*)d_in[0];
    const float* k = (const float*)d_in[1];
    const float* v = (const float*)d_in[2];
    float* o       = (float*)d_out;

    cudaFuncSetAttribute(swa_kernel, cudaFuncAttributeMaxDynamicSharedMemorySize, SMEM_BYTES);
    // grid: 2 batches * 64 tiles = 128 CTAs (one wave on 148 SMs)
    swa_kernel<<<128, THREADS, SMEM_BYTES>>>(q, k, v, o);
}